// round 17
// baseline (speedup 1.0000x reference)
#include <cuda_runtime.h>
#include <cstdint>

// WholeMask R17: CE-memset + precomputed-box painter.
// R16: paint issue-bound (53% issue, 4.2M instrs) — per-warp replicated
// setup (loads, round/clip, 2 runtime IDIV magic computations) dominated.
// Fix: prologue kernel computes per-slice {y1,x1,h,w,magics} once into 4KB
// __device__ scratch (h=0 == invalid). Paint warps: LDG.128 -> exit or
// umulhi/gather/store. Unsigned-compare bounds; exact magics, no clamps.

#define MH 28
#define MW 28
#define IMG 512
#define ROWS_PER_SLICE 152        // >= max box height in data; looped anyway

__device__ int4 g_boxes[2 * 1024];     // 2 x int4 per slice (<=1024 slices)

__global__ __launch_bounds__(128)
void box_prep_kernel(const float* __restrict__ bboxess,
                     const int*   __restrict__ counts,
                     int Kk, int BK)
{
    const int i = blockIdx.x * blockDim.x + threadIdx.x;
    if (i >= BK) return;
    const int b = i / Kk;
    const int k = i - b * Kk;
    const bool valid = (k < counts[b]);

    const float4 bb = __ldg(reinterpret_cast<const float4*>(bboxess) + i);
    int y1 = __float2int_rn(bb.x);         // half-even == jnp.round
    int x1 = __float2int_rn(bb.y);
    int y2 = __float2int_rn(bb.z);
    int x2 = __float2int_rn(bb.w);
    y1 = min(max(y1, 0), IMG - 1);
    x1 = min(max(x1, 0), IMG - 1);
    y2 = min(max(y2, y1 + 1), IMG);
    x2 = min(max(x2, x1 + 1), IMG);
    const int h = y2 - y1;
    const int w = x2 - x1;

    // Exact floor-div magics: umulhi(a, 0xFFFFFFFF/d + 1) == a/d for a*d < 2^32.
    const unsigned mh_magic = 0xFFFFFFFFu / (unsigned)h + 1;
    const unsigned mw_magic = 0xFFFFFFFFu / (unsigned)w + 1;

    g_boxes[2 * i]     = make_int4(y1, x1, valid ? h : 0, w);
    g_boxes[2 * i + 1] = make_int4((int)mh_magic, (int)mw_magic, 0, 0);
}

__global__ __launch_bounds__(256, 8)
void box_paint_kernel(const float* __restrict__ maskss,
                      float*       __restrict__ out)
{
    const int slice = blockIdx.x;
    const int4 a = g_boxes[2 * slice];         // y1, x1, h, w
    const int h = a.z;

    const int lane = threadIdx.x & 31;
    const int r0   = blockIdx.y * 8 + (threadIdx.x >> 5);
    if (r0 >= h) return;                       // invalid slice: h==0

    const int4 mg = g_boxes[2 * slice + 1];
    const unsigned mh_magic = (unsigned)mg.x;
    const unsigned mw_magic = (unsigned)mg.y;
    const int y1 = a.x, x1 = a.y, w = a.w;
    const int x2 = x1 + w;
    const int xa = x1 & ~3;

    const float* gm = maskss + (size_t)slice * (MH * MW);
    float* obase = out + (size_t)slice * (IMG * IMG);

    // Normally one iteration (h <= 152); loop keeps it general.
    for (int r = r0; r < h; r += ROWS_PER_SLICE) {
        const int sy = (int)__umulhi((unsigned)(r * MH), mh_magic);  // exact, <=27
        const float* mrow = gm + sy * MW;
        float* orow = obase + (size_t)(y1 + r) * IMG;

        for (int xq = xa + lane * 4; xq < x2; xq += 128) {
            float4 v;
            #pragma unroll
            for (int c = 0; c < 4; ++c) {
                const unsigned dx = (unsigned)(xq + c - x1);   // wraps if < x1
                float val = 0.f;
                if (dx < (unsigned)w) {                        // single compare
                    const int sx = (int)__umulhi(dx * MW, mw_magic);  // exact
                    val = __ldg(mrow + sx);
                }
                (&v.x)[c] = val;
            }
            *reinterpret_cast<float4*>(orow + xq) = v;   // zeros over zeros OK
        }
    }
}

extern "C" void kernel_launch(void* const* d_in, const int* in_sizes, int n_in,
                              void* d_out, int out_size)
{
    const float* bboxess = (const float*)d_in[0];   // (B,K,4) f32
    const int*   counts  = (const int*)  d_in[1];   // (B,1)   i32
    const float* maskss  = (const float*)d_in[2];   // (B,K,1,28,28) f32

    const int BK = in_sizes[0] / 4;                 // B*K
    const int Bv = in_sizes[1];                     // B
    const int Kk = BK / Bv;                         // K

    // 1) Per-slice box precompute (4KB scratch).
    box_prep_kernel<<<(BK + 127) / 128, 128>>>(bboxess, counts, Kk, BK);

    // 2) Bulk zero-fill via driver/CE memset (~6.7 TB/s, measured).
    cudaMemsetAsync(d_out, 0, (size_t)out_size * sizeof(float), 0);

    // 3) Paint box interiors: one row per warp.
    dim3 block(256);
    dim3 grid(BK, (ROWS_PER_SLICE + 7) / 8);   // 128 x 19 CTAs
    box_paint_kernel<<<grid, block>>>(maskss, (float*)d_out);
}